// round 12
// baseline (speedup 1.0000x reference)
#include <cuda_runtime.h>
#include <cuda_fp16.h>
#include <math.h>

#define Bn 4
#define Ln 1024
#define Dn 512
#define Hn 8
#define DH 64
#define BHn 32

// ---------------- scratch ----------------------------------------------------
// fp16 packed fragment layouts for m16n8k16:
//  B-pack (K, K', V^T, W): [ks][nf][lane 32][4 halfs]  -> one LDS.64 per frag
//  A-pack (Q|Q', x):       [rf][ks][lane 32][8 halfs]  -> one LDS.128 per frag
__device__ float  g_q[BHn * Ln * DH];         // fp32 (Q' build needs precision)
__device__ __half g_kpack[BHn * 16 * 4096];   // K
__device__ __half g_kppack[16 * 4096];        // K'  (bh-independent)
__device__ __half g_vpack[BHn * 16 * 4096];   // V^T
__device__ __half g_wpack[12 * 16 * 4096];    // W packed: [bn 12][kc 16][ks 2][nf 16][lane][4]

// ---------------- helpers ----------------------------------------------------
__device__ __forceinline__ unsigned fbits(float x) { return __float_as_uint(x); }

__device__ __forceinline__ void mma16(float* c, const uint4 a, const uint2 b) {
    asm volatile(
        "mma.sync.aligned.m16n8k16.row.col.f32.f16.f16.f32 "
        "{%0,%1,%2,%3}, {%4,%5,%6,%7}, {%8,%9}, {%0,%1,%2,%3};\n"
        : "+f"(c[0]), "+f"(c[1]), "+f"(c[2]), "+f"(c[3])
        : "r"(a.x), "r"(a.y), "r"(a.z), "r"(a.w), "r"(b.x), "r"(b.y));
}

__device__ __forceinline__ unsigned h2u(float2 f) {
    __half2 h = __floats2half2_rn(f.x, f.y);
    return *reinterpret_cast<unsigned*>(&h);
}

__device__ __forceinline__ void cpa16(unsigned dst, const void* src) {
    asm volatile("cp.async.cg.shared.global [%0], [%1], 16;\n" :: "r"(dst), "l"(src));
}
#define CP_COMMIT()  asm volatile("cp.async.commit_group;\n")
#define CP_WAIT(N)   asm volatile("cp.async.wait_group %0;\n" :: "n"(N))

// ---------------- kernel 0: pack W into fp16 B-frag layout --------------------
__global__ __launch_bounds__(256) void wpack_kernel(const float* __restrict__ W) {
    int flat = blockIdx.x * 256 + threadIdx.x;        // 0..393215, writes half2
    int e2   = flat & 1;
    int lane = (flat >> 1) & 31;
    int nf   = (flat >> 6) & 15;
    int ks   = (flat >> 10) & 1;
    int kc   = (flat >> 11) & 15;
    int bn   = flat >> 15;                            // 0..11
    int g = lane >> 2, c4 = lane & 3;
    int k = kc * 32 + ks * 16 + e2 * 8 + 2 * c4;
    int n = bn * 128 + nf * 8 + g;
    float v0 = W[(size_t)k * 1536 + n];
    float v1 = W[(size_t)(k + 1) * 1536 + n];
    size_t idx = ((size_t)((((bn * 16 + kc) * 2 + ks) * 16 + nf) * 32 + lane)) * 4 + e2 * 2;
    *(__half2*)(g_wpack + idx) = __floats2half2_rn(v0, v1);
}

// ---------------- kernel 1: K' table (fp16, packed) ---------------------------
__global__ void kp_kernel() {
    int kv = blockIdx.x;          // 0..1023
    int j  = threadIdx.x;         // 0..63 (K' column = attn k 64+j)
    int jj = (j < 32) ? j : (j - 32);
    float w = expf(-(float)(2 * jj) * 0.14391157f);
    float s, c;
    sincosf((float)kv * w, &s, &c);
    float val = (j < 32) ? c : s;
    int t = kv >> 6, nf = (kv >> 3) & 7, g = kv & 7;
    int ks = j >> 4, kd = j & 15;
    int c4 = (kd & 7) >> 1, hx = kd & 1, br = kd >> 3;
    g_kppack[t * 4096 + ((ks * 8 + nf) * 32 + g * 4 + c4) * 4 + br * 2 + hx] =
        __float2half_rn(val);
}

// ---------------- kernel 2: proj GEMM (fp16 mma) -> Q, packed K / V^T ---------
// 128x128 tile/block, K=512 in 16 chunks of 32; B from g_wpack via cp.async
// (double-buffered); A staged inline fp32->fp16 into packed A layout.
__global__ __launch_bounds__(256, 2) void proj_kernel(const float* __restrict__ x,
                                                      const float* __restrict__ W,
                                                      const float* __restrict__ bias) {
    (void)W;
    __shared__ __half As[4096];         // [rf 8][ks 2][lane 32][8]
    __shared__ __half Bsb[2][4096];     // [ks 2][nf 16][lane 32][4]
    int bn = blockIdx.x;                // 0..11
    int bm = blockIdx.y;                // 0..31
    int m0 = bm * 128, n0 = bn * 128;
    int tid = threadIdx.x, lane = tid & 31, wid = tid >> 5;
    int wm = wid >> 1, wn = wid & 1;    // 4 x 2 warps, 32m x 64n tiles
    int g = lane >> 2, c4 = lane & 3;

    const __half* wsrc = g_wpack + (size_t)bn * 16 * 4096;

    // prefetch B(0)
    {
        unsigned dst = (unsigned)__cvta_generic_to_shared(Bsb[0]);
        #pragma unroll
        for (int p = 0; p < 2; p++) {
            int idx = p * 256 + tid;
            cpa16(dst + idx * 16, wsrc + idx * 8);
        }
        CP_COMMIT();
    }

    float acc[2][8][4];
    #pragma unroll
    for (int i = 0; i < 2; i++)
        #pragma unroll
        for (int j = 0; j < 8; j++)
            #pragma unroll
            for (int q = 0; q < 4; q++) acc[i][j][q] = 0.0f;

    for (int chunk = 0; chunk < 16; chunk++) {
        __syncthreads();                 // As free, next B buffer free
        if (chunk < 15) {
            unsigned dst = (unsigned)__cvta_generic_to_shared(Bsb[(chunk + 1) & 1]);
            const __half* src = wsrc + (size_t)(chunk + 1) * 4096;
            #pragma unroll
            for (int p = 0; p < 2; p++) {
                int idx = p * 256 + tid;
                cpa16(dst + idx * 16, src + idx * 8);
            }
            CP_COMMIT();
        }
        // stage A(chunk): row r, 16 k's, fp32 -> fp16 packed
        {
            int r = tid >> 1, half_ = tid & 1;
            const float* src = x + (size_t)(m0 + r) * 512 + chunk * 32 + half_ * 16;
            float xa[16];
            #pragma unroll
            for (int i = 0; i < 16; i += 4) {
                float4 v = *(const float4*)(src + i);
                xa[i] = v.x; xa[i+1] = v.y; xa[i+2] = v.z; xa[i+3] = v.w;
            }
            int gg = r & 7, hi = (r >> 3) & 1, rf = r >> 4;
            #pragma unroll
            for (int i = 0; i < 16; i++) {
                int c4q = (i & 7) >> 1, hx = i & 1, khi = i >> 3;
                As[((rf * 2 + half_) * 32 + gg * 4 + c4q) * 8 + (khi * 2 + hi) * 2 + hx] =
                    __float2half_rn(xa[i]);
            }
        }
        if (chunk < 15) { CP_WAIT(1); } else { CP_WAIT(0); }
        __syncthreads();                 // A stores + B(chunk) visible

        const __half* Bc = Bsb[chunk & 1];
        #pragma unroll
        for (int ks = 0; ks < 2; ks++) {
            uint4 av[2];
            #pragma unroll
            for (int mi = 0; mi < 2; mi++)
                av[mi] = *(const uint4*)(As + (((wm * 2 + mi) * 2 + ks) * 32 + lane) * 8);
            #pragma unroll
            for (int ni = 0; ni < 8; ni++) {
                uint2 bv = *(const uint2*)(Bc + ((ks * 16 + wn * 8 + ni) * 32 + lane) * 4);
                mma16(acc[0][ni], av[0], bv);
                mma16(acc[1][ni], av[1], bv);
            }
        }
    }

    // epilogue: bias + scatter. Q fp32; K/V into fp16 packed frag layouts.
    #pragma unroll
    for (int mi = 0; mi < 2; mi++) {
        #pragma unroll
        for (int hh = 0; hh < 2; hh++) {
            int r = wm * 32 + mi * 16 + g + hh * 8;
            int mglob = m0 + r;
            int batch = mglob >> 10, l = mglob & 1023;
            int t = l >> 6;
            #pragma unroll
            for (int ni = 0; ni < 8; ni++) {
                int n = n0 + wn * 64 + ni * 8 + c4 * 2;
                float v0 = acc[mi][ni][hh * 2 + 0] + bias[n];
                float v1 = acc[mi][ni][hh * 2 + 1] + bias[n + 1];
                int h = n / 192;
                int rr = n - h * 192;
                int part = rr >> 6, d = rr & 63;   // d even
                size_t bh = (size_t)(batch * Hn + h);
                if (part == 0) {
                    *(float2*)(g_q + (bh * Ln + l) * DH + d) = make_float2(v0, v1);
                } else if (part == 1) {
                    int nf = (l >> 3) & 7, gg = l & 7;
                    int ks0 = d >> 4, kd = d & 15;
                    int c4k = (kd & 7) >> 1, br = kd >> 3;
                    size_t idx = (bh * 16 + t) * 4096 +
                                 (size_t)((ks0 * 8 + nf) * 32 + gg * 4 + c4k) * 4 + br * 2;
                    *(__half2*)(g_kpack + idx) = __floats2half2_rn(v0, v1);
                } else {
                    int kv6 = l & 63;
                    int ksv = kv6 >> 4, kdv = kv6 & 15;
                    int c4v = (kdv & 7) >> 1, hxv = kdv & 1, brv = kdv >> 3;
                    size_t base = (bh * 16 + t) * 4096;
                    g_vpack[base + (size_t)((ksv * 8 + (d >> 3)) * 32 + (d & 7) * 4 + c4v) * 4 +
                            brv * 2 + hxv] = __float2half_rn(v0);
                    int dd = d + 1;
                    g_vpack[base + (size_t)((ksv * 8 + (dd >> 3)) * 32 + (dd & 7) * 4 + c4v) * 4 +
                            brv * 2 + hxv] = __float2half_rn(v1);
                }
            }
        }
    }
}

// ---------------- kernel 3: fused attention (fp16 mma, 2 blocks/SM) ----------
#define PSP 72
#define SMB_QS 0            // 16384 halfs = 32768 B
#define SMB_BS 32768        //  8192 halfs = 16384 B
#define SMB_VS 49152        //  4096 halfs =  8192 B
#define SMB_PS 57344        //  128*72 floats = 36864 B
#define SMB_L  94208        //  128 floats = 512 B
#define ATT_SMEM 94720

__device__ __forceinline__ void stage_B(char* smc, int bh, int t, int tid) {
    unsigned dst = (unsigned)__cvta_generic_to_shared(smc + SMB_BS);
    const char* sk = (const char*)(g_kpack + ((size_t)bh * 16 + t) * 4096);
    const char* sp = (const char*)(g_kppack + (size_t)t * 4096);
    #pragma unroll
    for (int p = 0; p < 2; p++) {
        int idx = p * 256 + tid;
        cpa16(dst + idx * 16, sk + idx * 16);
        cpa16(dst + 8192 + idx * 16, sp + idx * 16);
    }
}
__device__ __forceinline__ void stage_V(char* smc, int bh, int t, int tid) {
    unsigned dst = (unsigned)__cvta_generic_to_shared(smc + SMB_VS);
    const char* sv = (const char*)(g_vpack + ((size_t)bh * 16 + t) * 4096);
    #pragma unroll
    for (int p = 0; p < 2; p++) {
        int idx = p * 256 + tid;
        cpa16(dst + idx * 16, sv + idx * 16);
    }
}

__global__ __launch_bounds__(256, 2) void attn_kernel(float* __restrict__ out) {
    extern __shared__ char smc[];
    __half* Qs  = (__half*)(smc + SMB_QS);   // A-pack [rf 8][ks 8][lane][8]
    __half* Bs  = (__half*)(smc + SMB_BS);   // B-pack [ks 8][nf 8][lane][4]
    __half* Vs  = (__half*)(smc + SMB_VS);   // B-pack [ks 4][nf 8][lane][4]
    float* Ps   = (float*)(smc + SMB_PS);    // [128][PSP]
    float* lrow = (float*)(smc + SMB_L);     // [128]
    int qt = blockIdx.x, bh = blockIdx.y;
    int q0 = qt * 128;
    const float* Qg = g_q + ((size_t)bh << 16);
    int tid = threadIdx.x, lane = tid & 31, wid = tid >> 5;
    int wm = wid >> 1, wn = wid & 1;          // 4 x 2 warps, 32x32 tiles
    int g = lane >> 2, c4 = lane & 3;

    stage_B(smc, bh, 0, tid);
    CP_COMMIT();                               // group: B(0)

    // ---- build Q | Q' (scaled 1/8) into fp16 A-pack ----
    {
        int r = tid >> 1;                      // 0..127
        int half_ = tid & 1;                   // 16 j's each
        const float* src = Qg + (size_t)(q0 + r) * 64 + half_ * 16;
        float qa[16], qb[16];
        #pragma unroll
        for (int i = 0; i < 16; i += 4) {
            float4 v = *(const float4*)(src + i);
            qa[i] = v.x; qa[i+1] = v.y; qa[i+2] = v.z; qa[i+3] = v.w;
            float4 u = *(const float4*)(src + 32 + i);
            qb[i] = u.x; qb[i+1] = u.y; qb[i+2] = u.z; qb[i+3] = u.w;
        }
        float pos = (float)(q0 + r);
        int gg = r & 7, hi = (r >> 3) & 1, rf = r >> 4;
        #pragma unroll
        for (int i = 0; i < 16; i++) {
            int j = half_ * 16 + i;
            float w = expf(-(float)(2 * j) * 0.14391157f);
            float s, c;
            sincosf(pos * w, &s, &c);
            float vals[4] = { 0.125f * qa[i], 0.125f * qb[i],
                              0.125f * (qa[i] * s + qb[i] * c),
                              0.125f * (qb[i] * s - qa[i] * c) };
            #pragma unroll
            for (int q = 0; q < 4; q++) {
                int cc = j + q * 32;
                int ks = cc >> 4, kd = cc & 15;
                int c4q = (kd & 7) >> 1, hx = kd & 1, khi = kd >> 3;
                Qs[((rf * 8 + ks) * 32 + gg * 4 + c4q) * 8 + (khi * 2 + hi) * 2 + hx] =
                    __float2half_rn(vals[q]);
            }
        }
        if (tid < 128) lrow[tid] = 0.0f;
    }

    float acco[2][4][4];
    #pragma unroll
    for (int mi = 0; mi < 2; mi++)
        #pragma unroll
        for (int j = 0; j < 4; j++)
            #pragma unroll
            for (int q = 0; q < 4; q++) acco[mi][j][q] = 0.0f;

    for (int kt = 0; kt < 16; kt++) {
        __syncthreads();                       // A: PV(kt-1) done with Vs/Ps
        stage_V(smc, bh, kt, tid);
        CP_COMMIT();                           // outstanding: {B(kt), V(kt)}
        CP_WAIT(1);                            // B(kt) arrived
        __syncthreads();                       // B: Bs (and Qs at kt=0) visible

        // ---- S = [Q|Q'] . [K|K']^T  (fp16 m16n8k16, k=128 in 8 steps) ----
        float accs[2][4][4];
        #pragma unroll
        for (int mi = 0; mi < 2; mi++)
            #pragma unroll
            for (int j = 0; j < 4; j++)
                #pragma unroll
                for (int q = 0; q < 4; q++) accs[mi][j][q] = 0.0f;
        #pragma unroll
        for (int ks = 0; ks < 8; ks++) {
            uint4 av[2];
            #pragma unroll
            for (int mi = 0; mi < 2; mi++)
                av[mi] = *(const uint4*)(Qs + (((wm * 2 + mi) * 8 + ks) * 32 + lane) * 8);
            #pragma unroll
            for (int ni = 0; ni < 4; ni++) {
                uint2 bv = *(const uint2*)(Bs + ((ks * 8 + wn * 4 + ni) * 32 + lane) * 4);
                mma16(accs[0][ni], av[0], bv);
                mma16(accs[1][ni], av[1], bv);
            }
        }

        // ---- P = exp(S); Ps stores; row sums ----
        #pragma unroll
        for (int mi = 0; mi < 2; mi++)
            #pragma unroll
            for (int hh = 0; hh < 2; hh++) {
                int r = wm * 32 + mi * 16 + g + hh * 8;
                float part = 0.0f;
                #pragma unroll
                for (int ni = 0; ni < 4; ni++) {
                    float p0 = __expf(accs[mi][ni][hh * 2 + 0]);
                    float p1 = __expf(accs[mi][ni][hh * 2 + 1]);
                    part += p0 + p1;
                    *(float2*)(Ps + r * PSP + wn * 32 + ni * 8 + c4 * 2) =
                        make_float2(p0, p1);
                }
                part += __shfl_xor_sync(0xffffffffu, part, 1);
                part += __shfl_xor_sync(0xffffffffu, part, 2);
                if (c4 == 0) atomicAdd(&lrow[r], part);
            }

        CP_WAIT(0);                            // V(kt) arrived
        __syncthreads();                       // C: Vs+Ps visible; Bs reads done
        if (kt < 15) {
            stage_B(smc, bh, kt + 1, tid);
            CP_COMMIT();                       // hidden under PV
        }

        // ---- O += P @ V  (fp16 m16n8k16, kv=64 in 4 steps) ----
        #pragma unroll
        for (int ks = 0; ks < 4; ks++) {
            int kk = ks * 16;
            uint4 ap[2];
            #pragma unroll
            for (int mi = 0; mi < 2; mi++) {
                int r = wm * 32 + mi * 16 + g;
                float2 f0 = *(const float2*)(Ps + r * PSP + kk + 2 * c4);
                float2 f1 = *(const float2*)(Ps + (r + 8) * PSP + kk + 2 * c4);
                float2 f2 = *(const float2*)(Ps + r * PSP + kk + 2 * c4 + 8);
                float2 f3 = *(const float2*)(Ps + (r + 8) * PSP + kk + 2 * c4 + 8);
                ap[mi] = make_uint4(h2u(f0), h2u(f1), h2u(f2), h2u(f3));
            }
            #pragma unroll
            for (int ni = 0; ni < 4; ni++) {
                uint2 bv = *(const uint2*)(Vs + ((ks * 8 + wn * 4 + ni) * 32 + lane) * 4);
                mma16(acco[0][ni], ap[0], bv);
                mma16(acco[1][ni], ap[1], bv);
            }
        }
    }

    // ---- epilogue: O / l, fused transpose to [B, L, D] ----
    int batch = bh >> 3, h = bh & 7;
    #pragma unroll
    for (int mi = 0; mi < 2; mi++)
        #pragma unroll
        for (int hh = 0; hh < 2; hh++) {
            int r = wm * 32 + mi * 16 + g + hh * 8;
            float inv = 1.0f / lrow[r];
            int l = q0 + r;
            #pragma unroll
            for (int ni = 0; ni < 4; ni++) {
                int d = wn * 32 + ni * 8 + c4 * 2;
                *(float2*)(out + ((size_t)(batch * Ln + l)) * Dn + h * DH + d) =
                    make_float2(acco[mi][ni][hh * 2] * inv,
                                acco[mi][ni][hh * 2 + 1] * inv);
            }
        }
}

// ---------------- launch ------------------------------------------------------
extern "C" void kernel_launch(void* const* d_in, const int* in_sizes, int n_in,
                              void* d_out, int out_size) {
    (void)in_sizes; (void)n_in; (void)out_size;
    const float* x    = (const float*)d_in[0];
    const float* W    = (const float*)d_in[1];
    const float* bias = (const float*)d_in[2];
    float* out = (float*)d_out;

    cudaFuncSetAttribute(attn_kernel,
                         cudaFuncAttributeMaxDynamicSharedMemorySize, ATT_SMEM);

    wpack_kernel<<<1536, 256>>>(W);
    kp_kernel<<<Ln, 64>>>();

    dim3 pg(12, 32);
    proj_kernel<<<pg, 256>>>(x, W, bias);

    dim3 ag(8, BHn);
    attn_kernel<<<ag, 256, ATT_SMEM>>>(out);
}

// round 13
// speedup vs baseline: 1.0743x; 1.0743x over previous
#include <cuda_runtime.h>
#include <cuda_fp16.h>
#include <math.h>

#define Bn 4
#define Ln 1024
#define Dn 512
#define Hn 8
#define DH 64
#define BHn 32

// ---------------- scratch ----------------------------------------------------
__device__ float  g_q[BHn * Ln * DH];         // fp32 (Q' build needs precision)
__device__ __half g_kpack[BHn * 16 * 4096];   // K   packed B-frags
__device__ __half g_kppack[16 * 4096];        // K'  packed (bh-independent)
__device__ __half g_vpack[BHn * 16 * 4096];   // V^T packed B-frags
__device__ __half g_wpack[12 * 16 * 4096];    // W packed: [bn][kc][ks 2][nf 16][lane][4]

// ---------------- helpers ----------------------------------------------------
__device__ __forceinline__ void mma16(float* c, const uint4 a, const uint2 b) {
    asm volatile(
        "mma.sync.aligned.m16n8k16.row.col.f32.f16.f16.f32 "
        "{%0,%1,%2,%3}, {%4,%5,%6,%7}, {%8,%9}, {%0,%1,%2,%3};\n"
        : "+f"(c[0]), "+f"(c[1]), "+f"(c[2]), "+f"(c[3])
        : "r"(a.x), "r"(a.y), "r"(a.z), "r"(a.w), "r"(b.x), "r"(b.y));
}

__device__ __forceinline__ unsigned h2u(float a, float b) {
    __half2 h = __floats2half2_rn(a, b);
    return *reinterpret_cast<unsigned*>(&h);
}

__device__ __forceinline__ void cpa16(unsigned dst, const void* src) {
    asm volatile("cp.async.cg.shared.global [%0], [%1], 16;\n" :: "r"(dst), "l"(src));
}
#define CP_COMMIT()  asm volatile("cp.async.commit_group;\n")
#define CP_WAIT(N)   asm volatile("cp.async.wait_group %0;\n" :: "n"(N))

// ---------------- kernel 0: pack W (coalesced via smem) -----------------------
// One block per (bn, kc): 32k x 128n tile -> 4096-half packed frag tile.
__global__ __launch_bounds__(256) void wpack_kernel(const float* __restrict__ W) {
    __shared__ float ws[32 * 128];
    int kc = blockIdx.x & 15, bn = blockIdx.x >> 4;
    int tid = threadIdx.x;
    // coalesced load: row r (32), cols cb..cb+15
    {
        int r = tid >> 3, cb = (tid & 7) * 16;
        const float* src = W + (size_t)(kc * 32 + r) * 1536 + bn * 128 + cb;
        #pragma unroll
        for (int i = 0; i < 4; i++) {
            float4 v = *(const float4*)(src + i * 4);
            float* d = ws + r * 128 + cb + i * 4;
            d[0] = v.x; d[1] = v.y; d[2] = v.z; d[3] = v.w;
        }
    }
    __syncthreads();
    // coalesced packed write: thread owns 16 consecutive halfs (8 half2)
    __half2* dst = (__half2*)(g_wpack + (size_t)(bn * 16 + kc) * 4096);
    #pragma unroll
    for (int j = 0; j < 8; j++) {
        int f = tid * 16 + j * 2;
        int e = f & 3;
        int lane = (f >> 2) & 31;
        int nf = (f >> 7) & 15;
        int ks = (f >> 11) & 1;
        int g = lane >> 2, c4 = lane & 3;
        int k = ks * 16 + (e >> 1) * 8 + 2 * c4;   // local k row in ws
        int n = nf * 8 + g;
        dst[f >> 1] = __floats2half2_rn(ws[k * 128 + n], ws[(k + 1) * 128 + n]);
    }
}

// ---------------- kernel 1: K' table (fp16, packed) ---------------------------
__global__ void kp_kernel() {
    int kv = blockIdx.x;          // 0..1023
    int j  = threadIdx.x;         // 0..63 (K' column = attn k 64+j)
    int jj = (j < 32) ? j : (j - 32);
    float w = expf(-(float)(2 * jj) * 0.14391157f);
    float s, c;
    sincosf((float)kv * w, &s, &c);
    float val = (j < 32) ? c : s;
    int t = kv >> 6, nf = (kv >> 3) & 7, g = kv & 7;
    int ks = j >> 4, kd = j & 15;
    int c4 = (kd & 7) >> 1, hx = kd & 1, br = kd >> 3;
    g_kppack[t * 4096 + ((ks * 8 + nf) * 32 + g * 4 + c4) * 4 + br * 2 + hx] =
        __float2half_rn(val);
}

// ---------------- kernel 2: proj GEMM (fp16 mma) -> Q, packed K / V^T ---------
__global__ __launch_bounds__(256, 2) void proj_kernel(const float* __restrict__ x,
                                                      const float* __restrict__ bias) {
    __shared__ __half As[4096];         // [rf 8][ks 2][lane 32][8]
    __shared__ __half Bsb[2][4096];     // [ks 2][nf 16][lane 32][4]
    int bn = blockIdx.x;                // 0..11
    int bm = blockIdx.y;                // 0..31
    int m0 = bm * 128, n0 = bn * 128;
    int tid = threadIdx.x, lane = tid & 31, wid = tid >> 5;
    int wm = wid >> 1, wn = wid & 1;    // 4 x 2 warps, 32m x 64n tiles
    int g = lane >> 2, c4 = lane & 3;

    const __half* wsrc = g_wpack + (size_t)bn * 16 * 4096;

    {
        unsigned dst = (unsigned)__cvta_generic_to_shared(Bsb[0]);
        #pragma unroll
        for (int p = 0; p < 2; p++) {
            int idx = p * 256 + tid;
            cpa16(dst + idx * 16, wsrc + idx * 8);
        }
        CP_COMMIT();
    }

    float acc[2][8][4];
    #pragma unroll
    for (int i = 0; i < 2; i++)
        #pragma unroll
        for (int j = 0; j < 8; j++)
            #pragma unroll
            for (int q = 0; q < 4; q++) acc[i][j][q] = 0.0f;

    for (int chunk = 0; chunk < 16; chunk++) {
        __syncthreads();
        if (chunk < 15) {
            unsigned dst = (unsigned)__cvta_generic_to_shared(Bsb[(chunk + 1) & 1]);
            const __half* src = wsrc + (size_t)(chunk + 1) * 4096;
            #pragma unroll
            for (int p = 0; p < 2; p++) {
                int idx = p * 256 + tid;
                cpa16(dst + idx * 16, src + idx * 8);
            }
            CP_COMMIT();
        }
        {
            int r = tid >> 1, half_ = tid & 1;
            const float* src = x + (size_t)(m0 + r) * 512 + chunk * 32 + half_ * 16;
            float xa[16];
            #pragma unroll
            for (int i = 0; i < 16; i += 4) {
                float4 v = *(const float4*)(src + i);
                xa[i] = v.x; xa[i+1] = v.y; xa[i+2] = v.z; xa[i+3] = v.w;
            }
            int gg = r & 7, hi = (r >> 3) & 1, rf = r >> 4;
            #pragma unroll
            for (int i = 0; i < 16; i++) {
                int c4q = (i & 7) >> 1, hx = i & 1, khi = i >> 3;
                As[((rf * 2 + half_) * 32 + gg * 4 + c4q) * 8 + (khi * 2 + hi) * 2 + hx] =
                    __float2half_rn(xa[i]);
            }
        }
        if (chunk < 15) { CP_WAIT(1); } else { CP_WAIT(0); }
        __syncthreads();

        const __half* Bc = Bsb[chunk & 1];
        #pragma unroll
        for (int ks = 0; ks < 2; ks++) {
            uint4 av[2];
            #pragma unroll
            for (int mi = 0; mi < 2; mi++)
                av[mi] = *(const uint4*)(As + (((wm * 2 + mi) * 2 + ks) * 32 + lane) * 8);
            #pragma unroll
            for (int ni = 0; ni < 8; ni++) {
                uint2 bv = *(const uint2*)(Bc + ((ks * 16 + wn * 8 + ni) * 32 + lane) * 4);
                mma16(acc[0][ni], av[0], bv);
                mma16(acc[1][ni], av[1], bv);
            }
        }
    }

    // epilogue: bias + scatter. Q fp32; K/V into fp16 packed frag layouts.
    #pragma unroll
    for (int mi = 0; mi < 2; mi++) {
        #pragma unroll
        for (int hh = 0; hh < 2; hh++) {
            int r = wm * 32 + mi * 16 + g + hh * 8;
            int mglob = m0 + r;
            int batch = mglob >> 10, l = mglob & 1023;
            int t = l >> 6;
            #pragma unroll
            for (int ni = 0; ni < 8; ni++) {
                int n = n0 + wn * 64 + ni * 8 + c4 * 2;
                float v0 = acc[mi][ni][hh * 2 + 0] + bias[n];
                float v1 = acc[mi][ni][hh * 2 + 1] + bias[n + 1];
                int h = n / 192;
                int rr = n - h * 192;
                int part = rr >> 6, d = rr & 63;   // d even
                size_t bh = (size_t)(batch * Hn + h);
                if (part == 0) {
                    *(float2*)(g_q + (bh * Ln + l) * DH + d) = make_float2(v0, v1);
                } else if (part == 1) {
                    int nf = (l >> 3) & 7, gg = l & 7;
                    int ks0 = d >> 4, kd = d & 15;
                    int c4k = (kd & 7) >> 1, br = kd >> 3;
                    size_t idx = (bh * 16 + t) * 4096 +
                                 (size_t)((ks0 * 8 + nf) * 32 + gg * 4 + c4k) * 4 + br * 2;
                    *(__half2*)(g_kpack + idx) = __floats2half2_rn(v0, v1);
                } else {
                    int kv6 = l & 63;
                    int ksv = kv6 >> 4, kdv = kv6 & 15;
                    int c4v = (kdv & 7) >> 1, hxv = kdv & 1, brv = kdv >> 3;
                    size_t base = (bh * 16 + t) * 4096;
                    g_vpack[base + (size_t)((ksv * 8 + (d >> 3)) * 32 + (d & 7) * 4 + c4v) * 4 +
                            brv * 2 + hxv] = __float2half_rn(v0);
                    int dd = d + 1;
                    g_vpack[base + (size_t)((ksv * 8 + (dd >> 3)) * 32 + (dd & 7) * 4 + c4v) * 4 +
                            brv * 2 + hxv] = __float2half_rn(v1);
                }
            }
        }
    }
}

// ---------------- kernel 3: fused attention, register-resident P --------------
// 8 warps x (16 q-rows x 64 kv): S C-frags == PV A-frags -> no P smem trip.
#define SMB_QS 0            // 16384 halfs = 32768 B
#define SMB_BS 32768        //  8192 halfs = 16384 B
#define SMB_VS 49152        //  4096 halfs =  8192 B
#define ATT_SMEM 57344

__device__ __forceinline__ void stage_B(char* smc, int bh, int t, int tid) {
    unsigned dst = (unsigned)__cvta_generic_to_shared(smc + SMB_BS);
    const char* sk = (const char*)(g_kpack + ((size_t)bh * 16 + t) * 4096);
    const char* sp = (const char*)(g_kppack + (size_t)t * 4096);
    #pragma unroll
    for (int p = 0; p < 2; p++) {
        int idx = p * 256 + tid;
        cpa16(dst + idx * 16, sk + idx * 16);
        cpa16(dst + 8192 + idx * 16, sp + idx * 16);
    }
}
__device__ __forceinline__ void stage_V(char* smc, int bh, int t, int tid) {
    unsigned dst = (unsigned)__cvta_generic_to_shared(smc + SMB_VS);
    const char* sv = (const char*)(g_vpack + ((size_t)bh * 16 + t) * 4096);
    #pragma unroll
    for (int p = 0; p < 2; p++) {
        int idx = p * 256 + tid;
        cpa16(dst + idx * 16, sv + idx * 16);
    }
}

__global__ __launch_bounds__(256, 2) void attn_kernel(float* __restrict__ out) {
    extern __shared__ char smc[];
    __half* Qs = (__half*)(smc + SMB_QS);   // A-pack [rf 8][ks 8][lane][8]
    __half* Bs = (__half*)(smc + SMB_BS);   // B-pack [ks 8][nf 8][lane][4]
    __half* Vs = (__half*)(smc + SMB_VS);   // B-pack [ks 4][nf 8][lane][4]
    int qt = blockIdx.x, bh = blockIdx.y;
    int q0 = qt * 128;
    const float* Qg = g_q + ((size_t)bh << 16);
    int tid = threadIdx.x, lane = tid & 31, wid = tid >> 5;   // wm = wid (rf)
    int g = lane >> 2, c4 = lane & 3;

    stage_B(smc, bh, 0, tid);
    CP_COMMIT();                               // group: B(0)

    // ---- build Q | Q' (scaled 1/8) into fp16 A-pack ----
    {
        int r = tid >> 1;                      // 0..127
        int half_ = tid & 1;                   // 16 j's each
        const float* src = Qg + (size_t)(q0 + r) * 64 + half_ * 16;
        float qa[16], qb[16];
        #pragma unroll
        for (int i = 0; i < 16; i += 4) {
            float4 v = *(const float4*)(src + i);
            qa[i] = v.x; qa[i+1] = v.y; qa[i+2] = v.z; qa[i+3] = v.w;
            float4 u = *(const float4*)(src + 32 + i);
            qb[i] = u.x; qb[i+1] = u.y; qb[i+2] = u.z; qb[i+3] = u.w;
        }
        float pos = (float)(q0 + r);
        int gg = r & 7, hi = (r >> 3) & 1, rf = r >> 4;
        #pragma unroll
        for (int i = 0; i < 16; i++) {
            int j = half_ * 16 + i;
            float w = expf(-(float)(2 * j) * 0.14391157f);
            float s, c;
            sincosf(pos * w, &s, &c);
            float vals[4] = { 0.125f * qa[i], 0.125f * qb[i],
                              0.125f * (qa[i] * s + qb[i] * c),
                              0.125f * (qb[i] * s - qa[i] * c) };
            #pragma unroll
            for (int q = 0; q < 4; q++) {
                int cc = j + q * 32;
                int ks = cc >> 4, kd = cc & 15;
                int c4q = (kd & 7) >> 1, hx = kd & 1, khi = kd >> 3;
                Qs[((rf * 8 + ks) * 32 + gg * 4 + c4q) * 8 + (khi * 2 + hi) * 2 + hx] =
                    __float2half_rn(vals[q]);
            }
        }
    }

    float acco[8][4];
    #pragma unroll
    for (int j = 0; j < 8; j++)
        #pragma unroll
        for (int q = 0; q < 4; q++) acco[j][q] = 0.0f;
    float rs0 = 0.0f, rs1 = 0.0f;              // row sums (rows g, g+8)

    for (int kt = 0; kt < 16; kt++) {
        __syncthreads();                       // A: prev PV done with Vs (kt0: Qs built)
        stage_V(smc, bh, kt, tid);
        CP_COMMIT();                           // outstanding: {B(kt), V(kt)}
        CP_WAIT(1);                            // B(kt) arrived
        __syncthreads();                       // B: Bs (and Qs at kt=0) visible

        // ---- S = [Q|Q'] . [K|K']^T : warp tile 16 x 64, k=128 ----
        float accs[8][4];
        #pragma unroll
        for (int j = 0; j < 8; j++)
            #pragma unroll
            for (int q = 0; q < 4; q++) accs[j][q] = 0.0f;
        #pragma unroll
        for (int ks = 0; ks < 8; ks++) {
            uint4 av = *(const uint4*)(Qs + (((wid * 8 + ks) * 32 + lane)) * 8);
            #pragma unroll
            for (int ni = 0; ni < 8; ni++) {
                uint2 bv = *(const uint2*)(Bs + ((ks * 8 + ni) * 32 + lane) * 4);
                mma16(accs[ni], av, bv);
            }
        }

        // ---- P = exp(S) in registers; C-frags -> PV A-frags; row sums ----
        uint4 ap[4];
        #pragma unroll
        for (int k2 = 0; k2 < 4; k2++) {
            float e0 = __expf(accs[2 * k2][0]);
            float e1 = __expf(accs[2 * k2][1]);
            float e2 = __expf(accs[2 * k2][2]);
            float e3 = __expf(accs[2 * k2][3]);
            float f0 = __expf(accs[2 * k2 + 1][0]);
            float f1 = __expf(accs[2 * k2 + 1][1]);
            float f2 = __expf(accs[2 * k2 + 1][2]);
            float f3 = __expf(accs[2 * k2 + 1][3]);
            rs0 += (e0 + e1) + (f0 + f1);
            rs1 += (e2 + e3) + (f2 + f3);
            ap[k2] = make_uint4(h2u(e0, e1), h2u(e2, e3), h2u(f0, f1), h2u(f2, f3));
        }

        CP_WAIT(0);                            // V(kt) arrived
        __syncthreads();                       // C: Vs visible; Bs reads retired
        if (kt < 15) {
            stage_B(smc, bh, kt + 1, tid);
            CP_COMMIT();                       // hidden under PV
        }

        // ---- O += P @ V : kv=64 in 4 k-chunks, register A ----
        #pragma unroll
        for (int k2 = 0; k2 < 4; k2++) {
            #pragma unroll
            for (int ni = 0; ni < 8; ni++) {
                uint2 bv = *(const uint2*)(Vs + ((k2 * 8 + ni) * 32 + lane) * 4);
                mma16(acco[ni], ap[k2], bv);
            }
        }
    }

    // ---- epilogue: quad-reduce row sums, O / l, fused transpose ----
    rs0 += __shfl_xor_sync(0xffffffffu, rs0, 1);
    rs0 += __shfl_xor_sync(0xffffffffu, rs0, 2);
    rs1 += __shfl_xor_sync(0xffffffffu, rs1, 1);
    rs1 += __shfl_xor_sync(0xffffffffu, rs1, 2);
    float inv0 = 1.0f / rs0, inv1 = 1.0f / rs1;
    int batch = bh >> 3, h = bh & 7;
    int l0 = q0 + wid * 16 + g;
    int l1 = l0 + 8;
    #pragma unroll
    for (int ni = 0; ni < 8; ni++) {
        int d = ni * 8 + c4 * 2;
        *(float2*)(out + ((size_t)(batch * Ln + l0)) * Dn + h * DH + d) =
            make_float2(acco[ni][0] * inv0, acco[ni][1] * inv0);
        *(float2*)(out + ((size_t)(batch * Ln + l1)) * Dn + h * DH + d) =
            make_float2(acco[ni][2] * inv1, acco[ni][3] * inv1);
    }
}

// ---------------- launch ------------------------------------------------------
extern "C" void kernel_launch(void* const* d_in, const int* in_sizes, int n_in,
                              void* d_out, int out_size) {
    (void)in_sizes; (void)n_in; (void)out_size;
    const float* x    = (const float*)d_in[0];
    const float* W    = (const float*)d_in[1];
    const float* bias = (const float*)d_in[2];
    float* out = (float*)d_out;

    cudaFuncSetAttribute(attn_kernel,
                         cudaFuncAttributeMaxDynamicSharedMemorySize, ATT_SMEM);

    wpack_kernel<<<192, 256>>>(W);
    kp_kernel<<<Ln, 64>>>();

    dim3 pg(12, 32);
    proj_kernel<<<pg, 256>>>(x, bias);

    dim3 ag(8, BHn);
    attn_kernel<<<ag, 256, ATT_SMEM>>>(out);
}

// round 14
// speedup vs baseline: 1.2452x; 1.1591x over previous
#include <cuda_runtime.h>
#include <cuda_fp16.h>
#include <math.h>

#define Bn 4
#define Ln 1024
#define Dn 512
#define Hn 8
#define DH 64
#define BHn 32

// ---------------- scratch ----------------------------------------------------
__device__ float  g_q[BHn * Ln * DH];         // fp32 (Q' build needs precision)
__device__ __half g_kpack[BHn * 16 * 4096];   // K   packed B-frags
__device__ __half g_kppack[16 * 4096];        // K'  packed (bh-independent)
__device__ __half g_vpack[BHn * 16 * 4096];   // V^T packed B-frags
__device__ __half g_wpack[12 * 16 * 4096];    // W packed: [bn][kc][ks 2][nf 16][lane][4]

// ---------------- helpers ----------------------------------------------------
__device__ __forceinline__ void mma16(float* c, const uint4 a, const uint2 b) {
    asm volatile(
        "mma.sync.aligned.m16n8k16.row.col.f32.f16.f16.f32 "
        "{%0,%1,%2,%3}, {%4,%5,%6,%7}, {%8,%9}, {%0,%1,%2,%3};\n"
        : "+f"(c[0]), "+f"(c[1]), "+f"(c[2]), "+f"(c[3])
        : "r"(a.x), "r"(a.y), "r"(a.z), "r"(a.w), "r"(b.x), "r"(b.y));
}

__device__ __forceinline__ unsigned h2u(float a, float b) {
    __half2 h = __floats2half2_rn(a, b);
    return *reinterpret_cast<unsigned*>(&h);
}

__device__ __forceinline__ void cpa16(unsigned dst, const void* src) {
    asm volatile("cp.async.cg.shared.global [%0], [%1], 16;\n" :: "r"(dst), "l"(src));
}
#define CP_COMMIT()  asm volatile("cp.async.commit_group;\n")
#define CP_WAIT(N)   asm volatile("cp.async.wait_group %0;\n" :: "n"(N))

// ---------------- kernel 0: pack W (coalesced via smem) -----------------------
__global__ __launch_bounds__(256) void wpack_kernel(const float* __restrict__ W) {
    __shared__ float ws[32 * 128];
    int kc = blockIdx.x & 15, bn = blockIdx.x >> 4;
    int tid = threadIdx.x;
    {
        int r = tid >> 3, cb = (tid & 7) * 16;
        const float* src = W + (size_t)(kc * 32 + r) * 1536 + bn * 128 + cb;
        #pragma unroll
        for (int i = 0; i < 4; i++) {
            float4 v = *(const float4*)(src + i * 4);
            float* d = ws + r * 128 + cb + i * 4;
            d[0] = v.x; d[1] = v.y; d[2] = v.z; d[3] = v.w;
        }
    }
    __syncthreads();
    __half2* dst = (__half2*)(g_wpack + (size_t)(bn * 16 + kc) * 4096);
    #pragma unroll
    for (int j = 0; j < 8; j++) {
        int f = tid * 16 + j * 2;
        int e = f & 3;
        int lane = (f >> 2) & 31;
        int nf = (f >> 7) & 15;
        int ks = (f >> 11) & 1;
        int g = lane >> 2, c4 = lane & 3;
        int k = ks * 16 + (e >> 1) * 8 + 2 * c4;
        int n = nf * 8 + g;
        dst[f >> 1] = __floats2half2_rn(ws[k * 128 + n], ws[(k + 1) * 128 + n]);
    }
}

// ---------------- kernel 1: K' table (fp16, packed) ---------------------------
__global__ void kp_kernel() {
    int kv = blockIdx.x;
    int j  = threadIdx.x;         // 0..63
    int jj = (j < 32) ? j : (j - 32);
    float w = expf(-(float)(2 * jj) * 0.14391157f);
    float s, c;
    sincosf((float)kv * w, &s, &c);
    float val = (j < 32) ? c : s;
    int t = kv >> 6, nf = (kv >> 3) & 7, g = kv & 7;
    int ks = j >> 4, kd = j & 15;
    int c4 = (kd & 7) >> 1, hx = kd & 1, br = kd >> 3;
    g_kppack[t * 4096 + ((ks * 8 + nf) * 32 + g * 4 + c4) * 4 + br * 2 + hx] =
        __float2half_rn(val);
}

// ---------------- kernel 2: proj GEMM (fp16 mma) -> Q, packed K / V^T ---------
__global__ __launch_bounds__(256, 2) void proj_kernel(const float* __restrict__ x,
                                                      const float* __restrict__ bias) {
    __shared__ __half As[4096];         // [rf 8][ks 2][lane 32][8]
    __shared__ __half Bsb[2][4096];     // [ks 2][nf 16][lane 32][4]
    int bn = blockIdx.x;                // 0..11
    int bm = blockIdx.y;                // 0..31
    int m0 = bm * 128, n0 = bn * 128;
    int tid = threadIdx.x, lane = tid & 31, wid = tid >> 5;
    int wm = wid >> 1, wn = wid & 1;
    int g = lane >> 2, c4 = lane & 3;

    const __half* wsrc = g_wpack + (size_t)bn * 16 * 4096;

    {
        unsigned dst = (unsigned)__cvta_generic_to_shared(Bsb[0]);
        #pragma unroll
        for (int p = 0; p < 2; p++) {
            int idx = p * 256 + tid;
            cpa16(dst + idx * 16, wsrc + idx * 8);
        }
        CP_COMMIT();
    }

    // A-staging decomposition: tid = rf*32 + gg*4 + half_*2 + cs
    int cs = tid & 1, half_ = (tid >> 1) & 1, gg = (tid >> 2) & 7, rfs = tid >> 5;
    int rowA = m0 + rfs * 16 + gg;

    float acc[2][8][4];
    #pragma unroll
    for (int i = 0; i < 2; i++)
        #pragma unroll
        for (int j = 0; j < 8; j++)
            #pragma unroll
            for (int q = 0; q < 4; q++) acc[i][j][q] = 0.0f;

    for (int chunk = 0; chunk < 16; chunk++) {
        __syncthreads();
        if (chunk < 15) {
            unsigned dst = (unsigned)__cvta_generic_to_shared(Bsb[(chunk + 1) & 1]);
            const __half* src = wsrc + (size_t)(chunk + 1) * 4096;
            #pragma unroll
            for (int p = 0; p < 2; p++) {
                int idx = p * 256 + tid;
                cpa16(dst + idx * 16, src + idx * 8);
            }
            CP_COMMIT();
        }
        // stage A(chunk): rows (rowA, rowA+8), k span cs*4 + {0..3, 8..11}
        {
            const float* s0 = x + (size_t)rowA * 512 + chunk * 32 + half_ * 16 + cs * 4;
            const float* s1 = s0 + 8 * 512;
            float4 v0 = *(const float4*)(s0);
            float4 v1 = *(const float4*)(s0 + 8);
            float4 v2 = *(const float4*)(s1);
            float4 v3 = *(const float4*)(s1 + 8);
            unsigned st0[4] = { h2u(v0.x, v0.y), h2u(v2.x, v2.y),
                                h2u(v1.x, v1.y), h2u(v3.x, v3.y) };
            unsigned st1[4] = { h2u(v0.z, v0.w), h2u(v2.z, v2.w),
                                h2u(v1.z, v1.w), h2u(v3.z, v3.w) };
            int gbase = (rfs * 2 + half_) * 32 + gg * 4 + 2 * cs;
            *(uint4*)(As + (size_t)gbase * 8) = *(uint4*)st0;
            *(uint4*)(As + (size_t)(gbase + 1) * 8) = *(uint4*)st1;
        }
        if (chunk < 15) { CP_WAIT(1); } else { CP_WAIT(0); }
        __syncthreads();

        const __half* Bc = Bsb[chunk & 1];
        #pragma unroll
        for (int ks = 0; ks < 2; ks++) {
            uint4 av[2];
            #pragma unroll
            for (int mi = 0; mi < 2; mi++)
                av[mi] = *(const uint4*)(As + (((wm * 2 + mi) * 2 + ks) * 32 + lane) * 8);
            #pragma unroll
            for (int ni = 0; ni < 8; ni++) {
                uint2 bv = *(const uint2*)(Bc + ((ks * 16 + wn * 8 + ni) * 32 + lane) * 4);
                mma16(acc[0][ni], av[0], bv);
                mma16(acc[1][ni], av[1], bv);
            }
        }
    }

    // epilogue: bias + scatter. Q fp32; K/V into fp16 packed frag layouts.
    #pragma unroll
    for (int mi = 0; mi < 2; mi++) {
        #pragma unroll
        for (int hh = 0; hh < 2; hh++) {
            int r = wm * 32 + mi * 16 + g + hh * 8;
            int mglob = m0 + r;
            int batch = mglob >> 10, l = mglob & 1023;
            int t = l >> 6;
            #pragma unroll
            for (int ni = 0; ni < 8; ni++) {
                int n = n0 + wn * 64 + ni * 8 + c4 * 2;
                float v0 = acc[mi][ni][hh * 2 + 0] + bias[n];
                float v1 = acc[mi][ni][hh * 2 + 1] + bias[n + 1];
                int h = n / 192;
                int rr = n - h * 192;
                int part = rr >> 6, d = rr & 63;   // d even
                size_t bh = (size_t)(batch * Hn + h);
                if (part == 0) {
                    *(float2*)(g_q + (bh * Ln + l) * DH + d) = make_float2(v0, v1);
                } else if (part == 1) {
                    int nf = (l >> 3) & 7, gg2 = l & 7;
                    int ks0 = d >> 4, kd = d & 15;
                    int c4k = (kd & 7) >> 1, br = kd >> 3;
                    size_t idx = (bh * 16 + t) * 4096 +
                                 (size_t)((ks0 * 8 + nf) * 32 + gg2 * 4 + c4k) * 4 + br * 2;
                    *(__half2*)(g_kpack + idx) = __floats2half2_rn(v0, v1);
                } else {
                    int kv6 = l & 63;
                    int ksv = kv6 >> 4, kdv = kv6 & 15;
                    int c4v = (kdv & 7) >> 1, hxv = kdv & 1, brv = kdv >> 3;
                    size_t base = (bh * 16 + t) * 4096;
                    g_vpack[base + (size_t)((ksv * 8 + (d >> 3)) * 32 + (d & 7) * 4 + c4v) * 4 +
                            brv * 2 + hxv] = __float2half_rn(v0);
                    int dd = d + 1;
                    g_vpack[base + (size_t)((ksv * 8 + (dd >> 3)) * 32 + (dd & 7) * 4 + c4v) * 4 +
                            brv * 2 + hxv] = __float2half_rn(v1);
                }
            }
        }
    }
}

// ---------------- kernel 3: fused attention, register-resident P --------------
#define SMB_QS 0            // 16384 halfs = 32768 B
#define SMB_BS 32768        //  8192 halfs = 16384 B
#define SMB_VS 49152        //  4096 halfs =  8192 B
#define ATT_SMEM 57344

__device__ __forceinline__ void stage_B(char* smc, int bh, int t, int tid) {
    unsigned dst = (unsigned)__cvta_generic_to_shared(smc + SMB_BS);
    const char* sk = (const char*)(g_kpack + ((size_t)bh * 16 + t) * 4096);
    const char* sp = (const char*)(g_kppack + (size_t)t * 4096);
    #pragma unroll
    for (int p = 0; p < 2; p++) {
        int idx = p * 256 + tid;
        cpa16(dst + idx * 16, sk + idx * 16);
        cpa16(dst + 8192 + idx * 16, sp + idx * 16);
    }
}
__device__ __forceinline__ void stage_V(char* smc, int bh, int t, int tid) {
    unsigned dst = (unsigned)__cvta_generic_to_shared(smc + SMB_VS);
    const char* sv = (const char*)(g_vpack + ((size_t)bh * 16 + t) * 4096);
    #pragma unroll
    for (int p = 0; p < 2; p++) {
        int idx = p * 256 + tid;
        cpa16(dst + idx * 16, sv + idx * 16);
    }
}

__global__ __launch_bounds__(256, 2) void attn_kernel(float* __restrict__ out) {
    extern __shared__ char smc[];
    __half* Qs = (__half*)(smc + SMB_QS);   // A-pack [rf 8][ks 8][lane][8]
    __half* Bs = (__half*)(smc + SMB_BS);   // B-pack [ks 8][nf 8][lane][4]
    __half* Vs = (__half*)(smc + SMB_VS);   // B-pack [ks 4][nf 8][lane][4]
    int qt = blockIdx.x, bh = blockIdx.y;
    int q0 = qt * 128;
    const float* Qg = g_q + ((size_t)bh << 16);
    int tid = threadIdx.x, lane = tid & 31, wid = tid >> 5;
    int g = lane >> 2, c4 = lane & 3;

    stage_B(smc, bh, 0, tid);
    CP_COMMIT();                               // group: B(0)

    // ---- build Q | Q' (scaled 1/8) into fp16 A-pack, vectorized stores ----
    // tid = rfq*32 + ggq*4 + jq : rows (r, r+8), j in [8*jq, 8*jq+8)
    {
        int jq = tid & 3, ggq = (tid >> 2) & 7, rfq = tid >> 5;
        int r = rfq * 16 + ggq;                 // and r+8
        int j0 = jq * 8;
        const float* s0 = Qg + (size_t)(q0 + r) * 64;
        const float* s1 = s0 + 8 * 64;
        float qa0[8], qb0[8], qa1[8], qb1[8];
        #pragma unroll
        for (int i = 0; i < 8; i += 4) {
            float4 v;
            v = *(const float4*)(s0 + j0 + i);      qa0[i]=v.x; qa0[i+1]=v.y; qa0[i+2]=v.z; qa0[i+3]=v.w;
            v = *(const float4*)(s0 + 32 + j0 + i); qb0[i]=v.x; qb0[i+1]=v.y; qb0[i+2]=v.z; qb0[i+3]=v.w;
            v = *(const float4*)(s1 + j0 + i);      qa1[i]=v.x; qa1[i+1]=v.y; qa1[i+2]=v.z; qa1[i+3]=v.w;
            v = *(const float4*)(s1 + 32 + j0 + i); qb1[i]=v.x; qb1[i+1]=v.y; qb1[i+2]=v.z; qb1[i+3]=v.w;
        }
        float pos0 = (float)(q0 + r);
        float pos1 = (float)(q0 + r + 8);
        int khi = jq & 1, kso = jq >> 1;
        #pragma unroll
        for (int m = 0; m < 4; m++) {
            float va0[2][4], va1[2][4];         // [i parity][quadrant]
            #pragma unroll
            for (int e = 0; e < 2; e++) {
                int i = 2 * m + e;
                int j = j0 + i;
                float w = expf(-(float)(2 * j) * 0.14391157f);
                float sa, ca, sb, cb;
                sincosf(pos0 * w, &sa, &ca);
                sincosf(pos1 * w, &sb, &cb);
                va0[e][0] = 0.125f * qa0[i];
                va0[e][1] = 0.125f * qb0[i];
                va0[e][2] = 0.125f * (qa0[i] * sa + qb0[i] * ca);
                va0[e][3] = 0.125f * (qb0[i] * sa - qa0[i] * ca);
                va1[e][0] = 0.125f * qa1[i];
                va1[e][1] = 0.125f * qb1[i];
                va1[e][2] = 0.125f * (qa1[i] * sb + qb1[i] * cb);
                va1[e][3] = 0.125f * (qb1[i] * sb - qa1[i] * cb);
            }
            #pragma unroll
            for (int q = 0; q < 4; q++) {
                int ks = 2 * q + kso;
                int group = (rfq * 8 + ks) * 32 + ggq * 4 + m;
                unsigned st[2] = { h2u(va0[0][q], va0[1][q]), h2u(va1[0][q], va1[1][q]) };
                *(uint2*)(Qs + (size_t)group * 8 + khi * 4) = *(uint2*)st;
            }
        }
    }

    float acco[8][4];
    #pragma unroll
    for (int j = 0; j < 8; j++)
        #pragma unroll
        for (int q = 0; q < 4; q++) acco[j][q] = 0.0f;
    float rs0 = 0.0f, rs1 = 0.0f;

    for (int kt = 0; kt < 16; kt++) {
        __syncthreads();                       // A: prev PV done with Vs
        stage_V(smc, bh, kt, tid);
        CP_COMMIT();                           // outstanding: {B(kt), V(kt)}
        CP_WAIT(1);                            // B(kt) arrived
        __syncthreads();                       // B: Bs (and Qs at kt=0) visible

        // ---- S: warp tile 16 x 64, k=128 ----
        float accs[8][4];
        #pragma unroll
        for (int j = 0; j < 8; j++)
            #pragma unroll
            for (int q = 0; q < 4; q++) accs[j][q] = 0.0f;
        #pragma unroll
        for (int ks = 0; ks < 8; ks++) {
            uint4 av = *(const uint4*)(Qs + (((wid * 8 + ks) * 32 + lane)) * 8);
            #pragma unroll
            for (int ni = 0; ni < 8; ni++) {
                uint2 bv = *(const uint2*)(Bs + ((ks * 8 + ni) * 32 + lane) * 4);
                mma16(accs[ni], av, bv);
            }
        }

        // ---- P = exp(S) in registers -> PV A-frags; row sums ----
        uint4 ap[4];
        #pragma unroll
        for (int k2 = 0; k2 < 4; k2++) {
            float e0 = __expf(accs[2 * k2][0]);
            float e1 = __expf(accs[2 * k2][1]);
            float e2 = __expf(accs[2 * k2][2]);
            float e3 = __expf(accs[2 * k2][3]);
            float f0 = __expf(accs[2 * k2 + 1][0]);
            float f1 = __expf(accs[2 * k2 + 1][1]);
            float f2 = __expf(accs[2 * k2 + 1][2]);
            float f3 = __expf(accs[2 * k2 + 1][3]);
            rs0 += (e0 + e1) + (f0 + f1);
            rs1 += (e2 + e3) + (f2 + f3);
            ap[k2] = make_uint4(h2u(e0, e1), h2u(e2, e3), h2u(f0, f1), h2u(f2, f3));
        }

        CP_WAIT(0);                            // V(kt) arrived
        __syncthreads();                       // C: Vs visible; Bs reads retired
        if (kt < 15) {
            stage_B(smc, bh, kt + 1, tid);
            CP_COMMIT();                       // hidden under PV
        }

        // ---- O += P @ V ----
        #pragma unroll
        for (int k2 = 0; k2 < 4; k2++) {
            #pragma unroll
            for (int ni = 0; ni < 8; ni++) {
                uint2 bv = *(const uint2*)(Vs + ((k2 * 8 + ni) * 32 + lane) * 4);
                mma16(acco[ni], ap[k2], bv);
            }
        }
    }

    // ---- epilogue: quad-reduce row sums, O / l, fused transpose ----
    rs0 += __shfl_xor_sync(0xffffffffu, rs0, 1);
    rs0 += __shfl_xor_sync(0xffffffffu, rs0, 2);
    rs1 += __shfl_xor_sync(0xffffffffu, rs1, 1);
    rs1 += __shfl_xor_sync(0xffffffffu, rs1, 2);
    float inv0 = 1.0f / rs0, inv1 = 1.0f / rs1;
    int batch = bh >> 3, h = bh & 7;
    int l0 = q0 + wid * 16 + g;
    int l1 = l0 + 8;
    #pragma unroll
    for (int ni = 0; ni < 8; ni++) {
        int d = ni * 8 + c4 * 2;
        *(float2*)(out + ((size_t)(batch * Ln + l0)) * Dn + h * DH + d) =
            make_float2(acco[ni][0] * inv0, acco[ni][1] * inv0);
        *(float2*)(out + ((size_t)(batch * Ln + l1)) * Dn + h * DH + d) =
            make_float2(acco[ni][2] * inv1, acco[ni][3] * inv1);
    }
}

// ---------------- launch ------------------------------------------------------
extern "C" void kernel_launch(void* const* d_in, const int* in_sizes, int n_in,
                              void* d_out, int out_size) {
    (void)in_sizes; (void)n_in; (void)out_size;
    const float* x    = (const float*)d_in[0];
    const float* W    = (const float*)d_in[1];
    const float* bias = (const float*)d_in[2];
    float* out = (float*)d_out;

    cudaFuncSetAttribute(attn_kernel,
                         cudaFuncAttributeMaxDynamicSharedMemorySize, ATT_SMEM);

    wpack_kernel<<<192, 256>>>(W);
    kp_kernel<<<Ln, 64>>>();

    dim3 pg(12, 32);
    proj_kernel<<<pg, 256>>>(x, bias);

    dim3 ag(8, BHn);
    attn_kernel<<<ag, 256, ATT_SMEM>>>(out);
}

// round 15
// speedup vs baseline: 1.3925x; 1.1183x over previous
#include <cuda_runtime.h>
#include <cuda_fp16.h>
#include <math.h>

#define Bn 4
#define Ln 1024
#define Dn 512
#define Hn 8
#define DH 64
#define BHn 32

// ---------------- scratch ----------------------------------------------------
__device__ float  g_q[BHn * Ln * DH];         // fp32 (Q' build needs precision)
__device__ __half g_kpack[BHn * 16 * 4096];   // K   packed B-frags
__device__ __half g_kppack[16 * 4096];        // K'  packed (bh-independent)
__device__ __half g_vpack[BHn * 16 * 4096];   // V^T packed B-frags
__device__ __half g_wpack[8 * 16 * 6144];     // W packed: [bn 8][kc 16][ks 2][nf 24][lane][4]

// ---------------- helpers ----------------------------------------------------
__device__ __forceinline__ void mma16(float* c, const uint4 a, const uint2 b) {
    asm volatile(
        "mma.sync.aligned.m16n8k16.row.col.f32.f16.f16.f32 "
        "{%0,%1,%2,%3}, {%4,%5,%6,%7}, {%8,%9}, {%0,%1,%2,%3};\n"
        : "+f"(c[0]), "+f"(c[1]), "+f"(c[2]), "+f"(c[3])
        : "r"(a.x), "r"(a.y), "r"(a.z), "r"(a.w), "r"(b.x), "r"(b.y));
}

__device__ __forceinline__ unsigned h2u(float a, float b) {
    __half2 h = __floats2half2_rn(a, b);
    return *reinterpret_cast<unsigned*>(&h);
}

__device__ __forceinline__ void cpa16(unsigned dst, const void* src) {
    asm volatile("cp.async.cg.shared.global [%0], [%1], 16;\n" :: "r"(dst), "l"(src));
}
#define CP_COMMIT()  asm volatile("cp.async.commit_group;\n")
#define CP_WAIT(N)   asm volatile("cp.async.wait_group %0;\n" :: "n"(N))

// ---------------- kernel 0: pack W for 192-wide tiles (via smem) --------------
// Block = (bn 0..7, kc 0..15): 32k x 192n tile -> 6144-half packed frag tile.
__global__ __launch_bounds__(256) void wpack_kernel(const float* __restrict__ W) {
    __shared__ float ws[32 * 192];
    int kc = blockIdx.x & 15, bn = blockIdx.x >> 4;
    int tid = threadIdx.x;
    {
        int r = tid >> 3, cb = (tid & 7) * 24;
        const float* src = W + (size_t)(kc * 32 + r) * 1536 + bn * 192 + cb;
        #pragma unroll
        for (int i = 0; i < 6; i++) {
            float4 v = *(const float4*)(src + i * 4);
            float* d = ws + r * 192 + cb + i * 4;
            d[0] = v.x; d[1] = v.y; d[2] = v.z; d[3] = v.w;
        }
    }
    __syncthreads();
    __half2* dst = (__half2*)(g_wpack + (size_t)(bn * 16 + kc) * 6144);
    #pragma unroll
    for (int j = 0; j < 12; j++) {
        int f = tid * 24 + j * 2;
        int e = f & 3;                    // 0 or 2
        int lane = (f >> 2) & 31;
        int grp = f >> 7;                 // 0..47
        int nf = grp % 24, ks = grp / 24;
        int g = lane >> 2, c4 = lane & 3;
        int k = ks * 16 + (e >> 1) * 8 + 2 * c4;
        int n = nf * 8 + g;
        dst[f >> 1] = __floats2half2_rn(ws[k * 192 + n], ws[(k + 1) * 192 + n]);
    }
}

// ---------------- kernel 1: K' table (fp16, packed) ---------------------------
__global__ void kp_kernel() {
    int kv = blockIdx.x;
    int j  = threadIdx.x;         // 0..63
    int jj = (j < 32) ? j : (j - 32);
    float w = expf(-(float)(2 * jj) * 0.14391157f);
    float s, c;
    sincosf((float)kv * w, &s, &c);
    float val = (j < 32) ? c : s;
    int t = kv >> 6, nf = (kv >> 3) & 7, g = kv & 7;
    int ks = j >> 4, kd = j & 15;
    int c4 = (kd & 7) >> 1, hx = kd & 1, br = kd >> 3;
    g_kppack[t * 4096 + ((ks * 8 + nf) * 32 + g * 4 + c4) * 4 + br * 2 + hx] =
        __float2half_rn(val);
}

// ---------------- kernel 2: proj GEMM (fp16 mma), 128x192 tiles ---------------
// Grid 8 x 32 = 256 blocks -> single wave at 2 blocks/SM.
__global__ __launch_bounds__(256, 2) void proj_kernel(const float* __restrict__ x,
                                                      const float* __restrict__ bias) {
    __shared__ __half As[4096];         // [rf 8][ks 2][lane 32][8]
    __shared__ __half Bsb[2][6144];     // [ks 2][nf 24][lane 32][4]
    int bn = blockIdx.x;                // 0..7
    int bm = blockIdx.y;                // 0..31
    int m0 = bm * 128, n0 = bn * 192;
    int tid = threadIdx.x, lane = tid & 31, wid = tid >> 5;
    int wm = wid >> 1, wn = wid & 1;    // 4 x 2 warps, 32m x 96n tiles
    int g = lane >> 2, c4 = lane & 3;

    const __half* wsrc = g_wpack + (size_t)bn * 16 * 6144;

    {
        unsigned dst = (unsigned)__cvta_generic_to_shared(Bsb[0]);
        #pragma unroll
        for (int p = 0; p < 3; p++) {
            int idx = p * 256 + tid;
            cpa16(dst + idx * 16, wsrc + idx * 8);
        }
        CP_COMMIT();
    }

    // A-staging decomposition: tid = rfs*32 + gg*4 + half_*2 + cs
    int cs = tid & 1, half_ = (tid >> 1) & 1, gg = (tid >> 2) & 7, rfs = tid >> 5;
    int rowA = m0 + rfs * 16 + gg;

    float acc[2][12][4];
    #pragma unroll
    for (int i = 0; i < 2; i++)
        #pragma unroll
        for (int j = 0; j < 12; j++)
            #pragma unroll
            for (int q = 0; q < 4; q++) acc[i][j][q] = 0.0f;

    for (int chunk = 0; chunk < 16; chunk++) {
        __syncthreads();
        if (chunk < 15) {
            unsigned dst = (unsigned)__cvta_generic_to_shared(Bsb[(chunk + 1) & 1]);
            const __half* src = wsrc + (size_t)(chunk + 1) * 6144;
            #pragma unroll
            for (int p = 0; p < 3; p++) {
                int idx = p * 256 + tid;
                cpa16(dst + idx * 16, src + idx * 8);
            }
            CP_COMMIT();
        }
        // stage A(chunk): rows (rowA, rowA+8), k span cs*4 + {0..3, 8..11}
        {
            const float* s0 = x + (size_t)rowA * 512 + chunk * 32 + half_ * 16 + cs * 4;
            const float* s1 = s0 + 8 * 512;
            float4 v0 = *(const float4*)(s0);
            float4 v1 = *(const float4*)(s0 + 8);
            float4 v2 = *(const float4*)(s1);
            float4 v3 = *(const float4*)(s1 + 8);
            unsigned st0[4] = { h2u(v0.x, v0.y), h2u(v2.x, v2.y),
                                h2u(v1.x, v1.y), h2u(v3.x, v3.y) };
            unsigned st1[4] = { h2u(v0.z, v0.w), h2u(v2.z, v2.w),
                                h2u(v1.z, v1.w), h2u(v3.z, v3.w) };
            int gbase = (rfs * 2 + half_) * 32 + gg * 4 + 2 * cs;
            *(uint4*)(As + (size_t)gbase * 8) = *(uint4*)st0;
            *(uint4*)(As + (size_t)(gbase + 1) * 8) = *(uint4*)st1;
        }
        if (chunk < 15) { CP_WAIT(1); } else { CP_WAIT(0); }
        __syncthreads();

        const __half* Bc = Bsb[chunk & 1];
        #pragma unroll
        for (int ks = 0; ks < 2; ks++) {
            uint4 av[2];
            #pragma unroll
            for (int mi = 0; mi < 2; mi++)
                av[mi] = *(const uint4*)(As + (((wm * 2 + mi) * 2 + ks) * 32 + lane) * 8);
            #pragma unroll
            for (int nj = 0; nj < 12; nj++) {
                uint2 bv = *(const uint2*)(Bc + ((ks * 24 + wn * 12 + nj) * 32 + lane) * 4);
                mma16(acc[0][nj], av[0], bv);
                mma16(acc[1][nj], av[1], bv);
            }
        }
    }

    // epilogue: bias + scatter. Q fp32; K/V into fp16 packed frag layouts.
    #pragma unroll
    for (int mi = 0; mi < 2; mi++) {
        #pragma unroll
        for (int hh = 0; hh < 2; hh++) {
            int r = wm * 32 + mi * 16 + g + hh * 8;
            int mglob = m0 + r;
            int batch = mglob >> 10, l = mglob & 1023;
            int t = l >> 6;
            #pragma unroll
            for (int nj = 0; nj < 12; nj++) {
                int n = n0 + wn * 96 + nj * 8 + c4 * 2;
                float v0 = acc[mi][nj][hh * 2 + 0] + bias[n];
                float v1 = acc[mi][nj][hh * 2 + 1] + bias[n + 1];
                int h = n / 192;
                int rr = n - h * 192;
                int part = rr >> 6, d = rr & 63;   // d even
                size_t bh = (size_t)(batch * Hn + h);
                if (part == 0) {
                    *(float2*)(g_q + (bh * Ln + l) * DH + d) = make_float2(v0, v1);
                } else if (part == 1) {
                    int nf = (l >> 3) & 7, gg2 = l & 7;
                    int ks0 = d >> 4, kd = d & 15;
                    int c4k = (kd & 7) >> 1, br = kd >> 3;
                    size_t idx = (bh * 16 + t) * 4096 +
                                 (size_t)((ks0 * 8 + nf) * 32 + gg2 * 4 + c4k) * 4 + br * 2;
                    *(__half2*)(g_kpack + idx) = __floats2half2_rn(v0, v1);
                } else {
                    int kv6 = l & 63;
                    int ksv = kv6 >> 4, kdv = kv6 & 15;
                    int c4v = (kdv & 7) >> 1, hxv = kdv & 1, brv = kdv >> 3;
                    size_t base = (bh * 16 + t) * 4096;
                    g_vpack[base + (size_t)((ksv * 8 + (d >> 3)) * 32 + (d & 7) * 4 + c4v) * 4 +
                            brv * 2 + hxv] = __float2half_rn(v0);
                    int dd = d + 1;
                    g_vpack[base + (size_t)((ksv * 8 + (dd >> 3)) * 32 + (dd & 7) * 4 + c4v) * 4 +
                            brv * 2 + hxv] = __float2half_rn(v1);
                }
            }
        }
    }
}

// ---------------- kernel 3: fused attention, register-resident P --------------
#define SMB_QS 0            // 16384 halfs = 32768 B
#define SMB_BS 32768        //  8192 halfs = 16384 B
#define SMB_VS 49152        //  4096 halfs =  8192 B
#define ATT_SMEM 57344

__device__ __forceinline__ void stage_B(char* smc, int bh, int t, int tid) {
    unsigned dst = (unsigned)__cvta_generic_to_shared(smc + SMB_BS);
    const char* sk = (const char*)(g_kpack + ((size_t)bh * 16 + t) * 4096);
    const char* sp = (const char*)(g_kppack + (size_t)t * 4096);
    #pragma unroll
    for (int p = 0; p < 2; p++) {
        int idx = p * 256 + tid;
        cpa16(dst + idx * 16, sk + idx * 16);
        cpa16(dst + 8192 + idx * 16, sp + idx * 16);
    }
}
__device__ __forceinline__ void stage_V(char* smc, int bh, int t, int tid) {
    unsigned dst = (unsigned)__cvta_generic_to_shared(smc + SMB_VS);
    const char* sv = (const char*)(g_vpack + ((size_t)bh * 16 + t) * 4096);
    #pragma unroll
    for (int p = 0; p < 2; p++) {
        int idx = p * 256 + tid;
        cpa16(dst + idx * 16, sv + idx * 16);
    }
}

__global__ __launch_bounds__(256, 2) void attn_kernel(float* __restrict__ out) {
    extern __shared__ char smc[];
    __half* Qs = (__half*)(smc + SMB_QS);   // A-pack [rf 8][ks 8][lane][8]
    __half* Bs = (__half*)(smc + SMB_BS);   // B-pack [ks 8][nf 8][lane][4]
    __half* Vs = (__half*)(smc + SMB_VS);   // B-pack [ks 4][nf 8][lane][4]
    int qt = blockIdx.x, bh = blockIdx.y;
    int q0 = qt * 128;
    const float* Qg = g_q + ((size_t)bh << 16);
    int tid = threadIdx.x, lane = tid & 31, wid = tid >> 5;
    int g = lane >> 2, c4 = lane & 3;

    stage_B(smc, bh, 0, tid);
    CP_COMMIT();                               // group: B(0)

    // ---- build Q | Q' (scaled 1/8) into fp16 A-pack, vectorized stores ----
    {
        int jq = tid & 3, ggq = (tid >> 2) & 7, rfq = tid >> 5;
        int r = rfq * 16 + ggq;                 // and r+8
        int j0 = jq * 8;
        const float* s0 = Qg + (size_t)(q0 + r) * 64;
        const float* s1 = s0 + 8 * 64;
        float qa0[8], qb0[8], qa1[8], qb1[8];
        #pragma unroll
        for (int i = 0; i < 8; i += 4) {
            float4 v;
            v = *(const float4*)(s0 + j0 + i);      qa0[i]=v.x; qa0[i+1]=v.y; qa0[i+2]=v.z; qa0[i+3]=v.w;
            v = *(const float4*)(s0 + 32 + j0 + i); qb0[i]=v.x; qb0[i+1]=v.y; qb0[i+2]=v.z; qb0[i+3]=v.w;
            v = *(const float4*)(s1 + j0 + i);      qa1[i]=v.x; qa1[i+1]=v.y; qa1[i+2]=v.z; qa1[i+3]=v.w;
            v = *(const float4*)(s1 + 32 + j0 + i); qb1[i]=v.x; qb1[i+1]=v.y; qb1[i+2]=v.z; qb1[i+3]=v.w;
        }
        float pos0 = (float)(q0 + r);
        float pos1 = (float)(q0 + r + 8);
        int khi = jq & 1, kso = jq >> 1;
        #pragma unroll
        for (int m = 0; m < 4; m++) {
            float va0[2][4], va1[2][4];
            #pragma unroll
            for (int e = 0; e < 2; e++) {
                int i = 2 * m + e;
                int j = j0 + i;
                float w = expf(-(float)(2 * j) * 0.14391157f);
                float sa, ca, sb, cb;
                sincosf(pos0 * w, &sa, &ca);
                sincosf(pos1 * w, &sb, &cb);
                va0[e][0] = 0.125f * qa0[i];
                va0[e][1] = 0.125f * qb0[i];
                va0[e][2] = 0.125f * (qa0[i] * sa + qb0[i] * ca);
                va0[e][3] = 0.125f * (qb0[i] * sa - qa0[i] * ca);
                va1[e][0] = 0.125f * qa1[i];
                va1[e][1] = 0.125f * qb1[i];
                va1[e][2] = 0.125f * (qa1[i] * sb + qb1[i] * cb);
                va1[e][3] = 0.125f * (qb1[i] * sb - qa1[i] * cb);
            }
            #pragma unroll
            for (int q = 0; q < 4; q++) {
                int ks = 2 * q + kso;
                int group = (rfq * 8 + ks) * 32 + ggq * 4 + m;
                unsigned st[2] = { h2u(va0[0][q], va0[1][q]), h2u(va1[0][q], va1[1][q]) };
                *(uint2*)(Qs + (size_t)group * 8 + khi * 4) = *(uint2*)st;
            }
        }
    }

    float acco[8][4];
    #pragma unroll
    for (int j = 0; j < 8; j++)
        #pragma unroll
        for (int q = 0; q < 4; q++) acco[j][q] = 0.0f;
    float rs0 = 0.0f, rs1 = 0.0f;

    for (int kt = 0; kt < 16; kt++) {
        __syncthreads();                       // A: prev PV done with Vs
        stage_V(smc, bh, kt, tid);
        CP_COMMIT();                           // outstanding: {B(kt), V(kt)}
        CP_WAIT(1);                            // B(kt) arrived
        __syncthreads();                       // B: Bs (and Qs at kt=0) visible

        // ---- S: warp tile 16 x 64, k=128 ----
        float accs[8][4];
        #pragma unroll
        for (int j = 0; j < 8; j++)
            #pragma unroll
            for (int q = 0; q < 4; q++) accs[j][q] = 0.0f;
        #pragma unroll
        for (int ks = 0; ks < 8; ks++) {
            uint4 av = *(const uint4*)(Qs + (((wid * 8 + ks) * 32 + lane)) * 8);
            #pragma unroll
            for (int ni = 0; ni < 8; ni++) {
                uint2 bv = *(const uint2*)(Bs + ((ks * 8 + ni) * 32 + lane) * 4);
                mma16(accs[ni], av, bv);
            }
        }

        // ---- P = exp(S) in registers -> PV A-frags; row sums ----
        uint4 ap[4];
        #pragma unroll
        for (int k2 = 0; k2 < 4; k2++) {
            float e0 = __expf(accs[2 * k2][0]);
            float e1 = __expf(accs[2 * k2][1]);
            float e2 = __expf(accs[2 * k2][2]);
            float e3 = __expf(accs[2 * k2][3]);
            float f0 = __expf(accs[2 * k2 + 1][0]);
            float f1 = __expf(accs[2 * k2 + 1][1]);
            float f2 = __expf(accs[2 * k2 + 1][2]);
            float f3 = __expf(accs[2 * k2 + 1][3]);
            rs0 += (e0 + e1) + (f0 + f1);
            rs1 += (e2 + e3) + (f2 + f3);
            ap[k2] = make_uint4(h2u(e0, e1), h2u(e2, e3), h2u(f0, f1), h2u(f2, f3));
        }

        CP_WAIT(0);                            // V(kt) arrived
        __syncthreads();                       // C: Vs visible; Bs reads retired
        if (kt < 15) {
            stage_B(smc, bh, kt + 1, tid);
            CP_COMMIT();                       // hidden under PV
        }

        // ---- O += P @ V ----
        #pragma unroll
        for (int k2 = 0; k2 < 4; k2++) {
            #pragma unroll
            for (int ni = 0; ni < 8; ni++) {
                uint2 bv = *(const uint2*)(Vs + ((k2 * 8 + ni) * 32 + lane) * 4);
                mma16(acco[ni], ap[k2], bv);
            }
        }
    }

    // ---- epilogue: quad-reduce row sums, O / l, fused transpose ----
    rs0 += __shfl_xor_sync(0xffffffffu, rs0, 1);
    rs0 += __shfl_xor_sync(0xffffffffu, rs0, 2);
    rs1 += __shfl_xor_sync(0xffffffffu, rs1, 1);
    rs1 += __shfl_xor_sync(0xffffffffu, rs1, 2);
    float inv0 = 1.0f / rs0, inv1 = 1.0f / rs1;
    int batch = bh >> 3, h = bh & 7;
    int l0 = q0 + wid * 16 + g;
    int l1 = l0 + 8;
    #pragma unroll
    for (int ni = 0; ni < 8; ni++) {
        int d = ni * 8 + c4 * 2;
        *(float2*)(out + ((size_t)(batch * Ln + l0)) * Dn + h * DH + d) =
            make_float2(acco[ni][0] * inv0, acco[ni][1] * inv0);
        *(float2*)(out + ((size_t)(batch * Ln + l1)) * Dn + h * DH + d) =
            make_float2(acco[ni][2] * inv1, acco[ni][3] * inv1);
    }
}

// ---------------- launch ------------------------------------------------------
extern "C" void kernel_launch(void* const* d_in, const int* in_sizes, int n_in,
                              void* d_out, int out_size) {
    (void)in_sizes; (void)n_in; (void)out_size;
    const float* x    = (const float*)d_in[0];
    const float* W    = (const float*)d_in[1];
    const float* bias = (const float*)d_in[2];
    float* out = (float*)d_out;

    cudaFuncSetAttribute(attn_kernel,
                         cudaFuncAttributeMaxDynamicSharedMemorySize, ATT_SMEM);

    wpack_kernel<<<128, 256>>>(W);
    kp_kernel<<<Ln, 64>>>();

    dim3 pg(8, 32);
    proj_kernel<<<pg, 256>>>(x, bias);

    dim3 ag(8, BHn);
    attn_kernel<<<ag, 256, ATT_SMEM>>>(out);
}